// round 4
// baseline (speedup 1.0000x reference)
#include <cuda_runtime.h>
#include <cstdint>

#define NN 100000
#define NE 1600000
#define F1 128
#define F2 64

// ---- scratch: __device__ globals, referenced ONLY from device code ----
__device__ int   g_is64;
__device__ int   g_src[NE];
__device__ int   g_dst[NE];
__device__ float g_deg[NN];
__device__ float g_dinv[NN];
__device__ float g_t1[(size_t)NN * F1];   // x @ W1^T
__device__ float g_agg1[(size_t)NN * F1]; // aggregated layer-1 (pre bias/relu)
__device__ float g_t2[(size_t)NN * F2];   // relu(agg1+b1) @ W2^T

__device__ __forceinline__ void red_add4(float* p, float4 v) {
    atomicAdd(p + 0, v.x);
    atomicAdd(p + 1, v.y);
    atomicAdd(p + 2, v.z);
    atomicAdd(p + 3, v.w);
}

// ---------------- dtype detection + index conversion ----------------
// If edge_index is int32 (JAX x64 disabled), reading as int64 fuses two
// indices -> huge values. Sample 1024 int64 reads; any out of [0,n) => int32.
__global__ void detect_kernel(const void* ei, int n, int e) {
    __shared__ int bad;
    if (threadIdx.x == 0) bad = 0;
    __syncthreads();
    const long long* p = (const long long*)ei;
    for (int i = threadIdx.x; i < 1024 && i < e; i += blockDim.x) {
        long long v = p[i];
        if (v < 0 || v >= n) bad = 1;
    }
    __syncthreads();
    if (threadIdx.x == 0) g_is64 = (bad == 0) ? 1 : 0;
}

__global__ void convert_kernel(const void* ei, int e) {
    int i = blockIdx.x * blockDim.x + threadIdx.x;
    if (i >= e) return;
    if (g_is64) {
        const long long* p = (const long long*)ei;
        g_src[i] = (int)p[i];
        g_dst[i] = (int)p[(size_t)e + i];
    } else {
        const int* p = (const int*)ei;
        g_src[i] = p[i];
        g_dst[i] = p[(size_t)e + i];
    }
}

// ---------------- degree / norm ----------------
__global__ void init_deg_kernel(int n) {
    int i = blockIdx.x * blockDim.x + threadIdx.x;
    if (i < n) g_deg[i] = 1.0f;   // self-loop
}

__global__ void deg_accum_kernel(int e) {
    int i = blockIdx.x * blockDim.x + threadIdx.x;
    if (i < e) atomicAdd(&g_deg[g_dst[i]], 1.0f);
}

__global__ void dinv_kernel(int n) {
    int i = blockIdx.x * blockDim.x + threadIdx.x;
    if (i < n) g_dinv[i] = rsqrtf(g_deg[i]);
}

// ---------------- SGEMM: out[r,c] = sum_k X[r,k] * W[c,k] ----------------
// LAYER1: X = x (arg), out = g_t1, FOUT=128.
// !LAYER1: X = g_agg1 (symbol), out = g_t2, FOUT=64, fused bias1+relu on load.
template<bool LAYER1>
__global__ void gemm_kernel(const float* __restrict__ Xarg,
                            const float* __restrict__ W,
                            const float* __restrict__ bias,
                            int n) {
    constexpr int FOUT = LAYER1 ? F1 : F2;
    constexpr int BM = 64;
    constexpr int BK = 16;
    constexpr int CG = FOUT / 4;      // threads along cols
    constexpr int RG = 256 / CG;      // row groups
    constexpr int TM = BM / RG;       // rows per thread

    const float* X = LAYER1 ? Xarg : (const float*)g_agg1;
    float* out = LAYER1 ? (float*)g_t1 : (float*)g_t2;

    __shared__ float Xs[BM][BK];
    __shared__ float Ws[BK][FOUT + 4];

    const int tid = threadIdx.x;
    const int tx = tid % CG;
    const int ty = tid / CG;
    const int row0 = blockIdx.x * BM;

    float acc[TM][4];
#pragma unroll
    for (int i = 0; i < TM; i++) { acc[i][0]=acc[i][1]=acc[i][2]=acc[i][3]=0.f; }

#pragma unroll
    for (int k0 = 0; k0 < 128; k0 += BK) {
        // X tile: 64x16 = 256 float4, one per thread
        {
            int r = tid >> 2;
            int c = (tid & 3) * 4;
            int gr = row0 + r;
            float4 v = make_float4(0.f, 0.f, 0.f, 0.f);
            if (gr < n) v = *(const float4*)&X[(size_t)gr * 128 + k0 + c];
            if (!LAYER1) {
                v.x = fmaxf(v.x + bias[k0 + c + 0], 0.f);
                v.y = fmaxf(v.y + bias[k0 + c + 1], 0.f);
                v.z = fmaxf(v.z + bias[k0 + c + 2], 0.f);
                v.w = fmaxf(v.w + bias[k0 + c + 3], 0.f);
            }
            *(float4*)&Xs[r][c] = v;
        }
        // W tile (transposed into smem): FOUT x 16
#pragma unroll
        for (int t = tid; t < FOUT * (BK / 4); t += 256) {
            int c  = t >> 2;          // output column
            int kc = (t & 3) * 4;
            float4 v = *(const float4*)&W[(size_t)c * 128 + k0 + kc];
            Ws[kc + 0][c] = v.x; Ws[kc + 1][c] = v.y;
            Ws[kc + 2][c] = v.z; Ws[kc + 3][c] = v.w;
        }
        __syncthreads();

#pragma unroll
        for (int kk = 0; kk < BK; kk++) {
            float4 b = *(const float4*)&Ws[kk][tx * 4];
#pragma unroll
            for (int i = 0; i < TM; i++) {
                float a = Xs[ty * TM + i][kk];
                acc[i][0] += a * b.x; acc[i][1] += a * b.y;
                acc[i][2] += a * b.z; acc[i][3] += a * b.w;
            }
        }
        __syncthreads();
    }

#pragma unroll
    for (int i = 0; i < TM; i++) {
        int r = row0 + ty * TM + i;
        if (r < n)
            *(float4*)&out[(size_t)r * FOUT + tx * 4] =
                make_float4(acc[i][0], acc[i][1], acc[i][2], acc[i][3]);
    }
}

// ---------------- layer 1: self-loop init + edge scatter ----------------
__global__ void init_agg1_kernel(int n) {
    int idx = blockIdx.x * blockDim.x + threadIdx.x;   // n*32 chunks
    if (idx >= n * 32) return;
    int i = idx >> 5;
    int c = (idx & 31) * 4;
    float s = g_dinv[i]; s *= s;
    float4 v = *(const float4*)&g_t1[(size_t)i * F1 + c];
    v.x *= s; v.y *= s; v.z *= s; v.w *= s;
    *(float4*)&g_agg1[(size_t)i * F1 + c] = v;
}

// one warp per edge; lane handles 4 floats -> full 128-feature row
__global__ void scatter1_kernel(int e) {
    int gid = blockIdx.x * blockDim.x + threadIdx.x;
    int w = gid >> 5;
    if (w >= e) return;
    int lane = threadIdx.x & 31;
    int src = g_src[w];
    int dst = g_dst[w];
    float norm = g_dinv[src] * g_dinv[dst];
    float4 v = *(const float4*)&g_t1[(size_t)src * F1 + lane * 4];
    v.x *= norm; v.y *= norm; v.z *= norm; v.w *= norm;
    red_add4(&g_agg1[(size_t)dst * F1 + lane * 4], v);
}

// ---------------- layer 2: self-loop+bias init + edge scatter ----------------
__global__ void init_out_kernel(const float* __restrict__ b2, float* __restrict__ out, int n) {
    int idx = blockIdx.x * blockDim.x + threadIdx.x;   // n*16 chunks
    if (idx >= n * 16) return;
    int i = idx >> 4;
    int c = (idx & 15) * 4;
    float s = g_dinv[i]; s *= s;
    float4 v = *(const float4*)&g_t2[(size_t)i * F2 + c];
    v.x = v.x * s + b2[c + 0];
    v.y = v.y * s + b2[c + 1];
    v.z = v.z * s + b2[c + 2];
    v.w = v.w * s + b2[c + 3];
    *(float4*)&out[(size_t)i * F2 + c] = v;
}

// half-warp per edge (64 features)
__global__ void scatter2_kernel(float* __restrict__ out, int e) {
    int gid = blockIdx.x * blockDim.x + threadIdx.x;
    int ed = gid >> 4;
    if (ed >= e) return;
    int c = (gid & 15) * 4;
    int src = g_src[ed];
    int dst = g_dst[ed];
    float norm = g_dinv[src] * g_dinv[dst];
    float4 v = *(const float4*)&g_t2[(size_t)src * F2 + c];
    v.x *= norm; v.y *= norm; v.z *= norm; v.w *= norm;
    red_add4(&out[(size_t)dst * F2 + c], v);
}

// ---------------- launch ----------------
extern "C" void kernel_launch(void* const* d_in, const int* in_sizes, int n_in,
                              void* d_out, int out_size) {
    const float* x  = (const float*)d_in[0];
    const void*  ei = d_in[1];
    const float* W1 = (const float*)d_in[2];
    const float* b1 = (const float*)d_in[3];
    const float* W2 = (const float*)d_in[4];
    const float* b2 = (const float*)d_in[5];
    float* out = (float*)d_out;

    const int n = in_sizes[0] / F1;       // 100000
    const int e = in_sizes[1] / 2;        // 1600000

    const int T = 256;
    // index decode (dtype-robust) + degree / norm
    detect_kernel<<<1, 256>>>(ei, n, e);
    convert_kernel<<<(e + T - 1) / T, T>>>(ei, e);
    init_deg_kernel<<<(n + T - 1) / T, T>>>(n);
    deg_accum_kernel<<<(e + T - 1) / T, T>>>(e);
    dinv_kernel<<<(n + T - 1) / T, T>>>(n);

    // layer 1
    gemm_kernel<true><<<(n + 63) / 64, 256>>>(x, W1, nullptr, n);
    init_agg1_kernel<<<(n * 32 + T - 1) / T, T>>>(n);
    scatter1_kernel<<<(int)(((long long)e * 32 + T - 1) / T), T>>>(e);

    // layer 2 (bias1 + relu fused into GEMM A-load)
    gemm_kernel<false><<<(n + 63) / 64, 256>>>(nullptr, W2, b1, n);
    init_out_kernel<<<(n * 16 + T - 1) / T, T>>>(b2, out, n);
    scatter2_kernel<<<(int)(((long long)e * 16 + T - 1) / T), T>>>(out, e);
}

// round 6
// speedup vs baseline: 1.7788x; 1.7788x over previous
#include <cuda_runtime.h>
#include <cstdint>

#define NN 100000
#define NE 1600000
#define F1 128
#define F2 64

// ---- scratch: __device__ globals, referenced ONLY from device code ----
__device__ int   g_is64;
__device__ int   g_src[NE];
__device__ int   g_dst[NE];
__device__ float g_deg[NN];
__device__ float g_dinv[NN];
__device__ float g_t1s[(size_t)NN * F1];  // (x @ W1^T) * dinv[row]  (pre-scaled messages)
__device__ float g_agg1[(size_t)NN * F1]; // aggregated layer-1 (pre bias/relu)
__device__ float g_t2s[(size_t)NN * F2];  // (relu(agg1+b1) @ W2^T) * dinv[row]

__device__ __forceinline__ void red_add_v4(float* p, float4 v) {
    asm volatile("red.global.add.v4.f32 [%0], {%1,%2,%3,%4};"
                 :: "l"(p), "f"(v.x), "f"(v.y), "f"(v.z), "f"(v.w) : "memory");
}

// ---------------- dtype detection ----------------
__global__ void detect_kernel(const void* ei, int n, int e) {
    __shared__ int bad;
    if (threadIdx.x == 0) bad = 0;
    __syncthreads();
    const long long* p = (const long long*)ei;
    for (int i = threadIdx.x; i < 1024 && i < e; i += blockDim.x) {
        long long v = p[i];
        if (v < 0 || v >= n) bad = 1;
    }
    __syncthreads();
    if (threadIdx.x == 0) g_is64 = (bad == 0) ? 1 : 0;
}

__global__ void init_deg_kernel(int n) {
    int i = blockIdx.x * blockDim.x + threadIdx.x;
    if (i < n) g_deg[i] = 1.0f;   // self-loop
}

// convert indices to int32 scratch AND accumulate degree in one pass
__global__ void convert_deg_kernel(const void* ei, int e) {
    int i = blockIdx.x * blockDim.x + threadIdx.x;
    if (i >= e) return;
    int s, d;
    if (g_is64) {
        const long long* p = (const long long*)ei;
        s = (int)p[i];
        d = (int)p[(size_t)e + i];
    } else {
        const int* p = (const int*)ei;
        s = p[i];
        d = p[(size_t)e + i];
    }
    g_src[i] = s;
    g_dst[i] = d;
    atomicAdd(&g_deg[d], 1.0f);
}

__global__ void dinv_kernel(int n) {
    int i = blockIdx.x * blockDim.x + threadIdx.x;
    if (i < n) g_dinv[i] = rsqrtf(g_deg[i]);
}

// ---------------- SGEMM: t[r,c] = sum_k X[r,k] * W[c,k] ----------------
// LAYER1: X = x (arg). Epilogue: g_t1s = t*dinv[r], g_agg1 = t*dinv[r]^2 (self-loop).
// !LAYER1: X = g_agg1, fused bias1+relu on load. Epilogue: g_t2s = t*dinv[r],
//          out = t*dinv[r]^2 + b2 (self-loop + final bias).
template<bool LAYER1>
__global__ void gemm_kernel(const float* __restrict__ Xarg,
                            const float* __restrict__ W,
                            const float* __restrict__ bias,   // b1 for layer2 load fusion
                            const float* __restrict__ b2,     // layer2 epilogue bias
                            float* __restrict__ outArg,       // d_out for layer2
                            int n) {
    constexpr int FOUT = LAYER1 ? F1 : F2;
    constexpr int BM = 64;
    constexpr int BK = 16;
    constexpr int CG = FOUT / 4;      // threads along cols
    constexpr int RG = 256 / CG;      // row groups
    constexpr int TM = BM / RG;       // rows per thread

    const float* X = LAYER1 ? Xarg : (const float*)g_agg1;
    float* outS = LAYER1 ? (float*)g_t1s : (float*)g_t2s;
    float* outA = LAYER1 ? (float*)g_agg1 : outArg;

    __shared__ float Xs[BM][BK];
    __shared__ float Ws[BK][FOUT + 4];

    const int tid = threadIdx.x;
    const int tx = tid % CG;
    const int ty = tid / CG;
    const int row0 = blockIdx.x * BM;

    float acc[TM][4];
#pragma unroll
    for (int i = 0; i < TM; i++) { acc[i][0]=acc[i][1]=acc[i][2]=acc[i][3]=0.f; }

#pragma unroll
    for (int k0 = 0; k0 < 128; k0 += BK) {
        {
            int r = tid >> 2;
            int c = (tid & 3) * 4;
            int gr = row0 + r;
            float4 v = make_float4(0.f, 0.f, 0.f, 0.f);
            if (gr < n) v = *(const float4*)&X[(size_t)gr * 128 + k0 + c];
            if (!LAYER1) {
                v.x = fmaxf(v.x + bias[k0 + c + 0], 0.f);
                v.y = fmaxf(v.y + bias[k0 + c + 1], 0.f);
                v.z = fmaxf(v.z + bias[k0 + c + 2], 0.f);
                v.w = fmaxf(v.w + bias[k0 + c + 3], 0.f);
            }
            *(float4*)&Xs[r][c] = v;
        }
#pragma unroll
        for (int t = tid; t < FOUT * (BK / 4); t += 256) {
            int c  = t >> 2;
            int kc = (t & 3) * 4;
            float4 v = *(const float4*)&W[(size_t)c * 128 + k0 + kc];
            Ws[kc + 0][c] = v.x; Ws[kc + 1][c] = v.y;
            Ws[kc + 2][c] = v.z; Ws[kc + 3][c] = v.w;
        }
        __syncthreads();

#pragma unroll
        for (int kk = 0; kk < BK; kk++) {
            float4 b = *(const float4*)&Ws[kk][tx * 4];
#pragma unroll
            for (int i = 0; i < TM; i++) {
                float a = Xs[ty * TM + i][kk];
                acc[i][0] += a * b.x; acc[i][1] += a * b.y;
                acc[i][2] += a * b.z; acc[i][3] += a * b.w;
            }
        }
        __syncthreads();
    }

#pragma unroll
    for (int i = 0; i < TM; i++) {
        int r = row0 + ty * TM + i;
        if (r < n) {
            float di = g_dinv[r];
            float4 s = make_float4(acc[i][0]*di, acc[i][1]*di, acc[i][2]*di, acc[i][3]*di);
            *(float4*)&outS[(size_t)r * FOUT + tx * 4] = s;
            float4 a = make_float4(s.x*di, s.y*di, s.z*di, s.w*di);
            if (!LAYER1) {
                a.x += b2[tx * 4 + 0]; a.y += b2[tx * 4 + 1];
                a.z += b2[tx * 4 + 2]; a.w += b2[tx * 4 + 3];
            }
            *(float4*)&outA[(size_t)r * FOUT + tx * 4] = a;
        }
    }
}

// ---------------- edge scatters ----------------
// one warp per edge; lane handles 4 floats -> full 128-feature row
__global__ void scatter1_kernel(int e) {
    int gid = blockIdx.x * blockDim.x + threadIdx.x;
    int w = gid >> 5;
    if (w >= e) return;
    int lane = threadIdx.x & 31;
    int src = g_src[w];
    int dst = g_dst[w];
    float nd = g_dinv[dst];                 // src scale already folded into t1s
    float4 v = *(const float4*)&g_t1s[(size_t)src * F1 + lane * 4];
    v.x *= nd; v.y *= nd; v.z *= nd; v.w *= nd;
    red_add_v4(&g_agg1[(size_t)dst * F1 + lane * 4], v);
}

// half-warp per edge (64 features)
__global__ void scatter2_kernel(float* __restrict__ out, int e) {
    int gid = blockIdx.x * blockDim.x + threadIdx.x;
    int ed = gid >> 4;
    if (ed >= e) return;
    int c = (gid & 15) * 4;
    int src = g_src[ed];
    int dst = g_dst[ed];
    float nd = g_dinv[dst];
    float4 v = *(const float4*)&g_t2s[(size_t)src * F2 + c];
    v.x *= nd; v.y *= nd; v.z *= nd; v.w *= nd;
    red_add_v4(&out[(size_t)dst * F2 + c], v);
}

// ---------------- launch ----------------
extern "C" void kernel_launch(void* const* d_in, const int* in_sizes, int n_in,
                              void* d_out, int out_size) {
    const float* x  = (const float*)d_in[0];
    const void*  ei = d_in[1];
    const float* W1 = (const float*)d_in[2];
    const float* b1 = (const float*)d_in[3];
    const float* W2 = (const float*)d_in[4];
    const float* b2 = (const float*)d_in[5];
    float* out = (float*)d_out;

    const int n = in_sizes[0] / F1;       // 100000
    const int e = in_sizes[1] / 2;        // 1600000

    const int T = 256;
    // index decode + degree / norm
    detect_kernel<<<1, 256>>>(ei, n, e);
    init_deg_kernel<<<(n + T - 1) / T, T>>>(n);
    convert_deg_kernel<<<(e + T - 1) / T, T>>>(ei, e);
    dinv_kernel<<<(n + T - 1) / T, T>>>(n);

    // layer 1 (epilogue writes t1s + self-loop-initialized agg1)
    gemm_kernel<true><<<(n + 63) / 64, 256>>>(x, W1, nullptr, nullptr, nullptr, n);
    scatter1_kernel<<<(int)(((long long)e * 32 + T - 1) / T), T>>>(e);

    // layer 2 (bias1+relu fused on load; epilogue writes t2s + self-loop+b2 into out)
    gemm_kernel<false><<<(n + 63) / 64, 256>>>(nullptr, W2, b1, b2, out, n);
    scatter2_kernel<<<(int)(((long long)e * 16 + T - 1) / T), T>>>(out, e);
}

// round 8
// speedup vs baseline: 1.9290x; 1.0845x over previous
#include <cuda_runtime.h>
#include <cstdint>

#define NN 100000
#define NE 1600000
#define F1 128
#define F2 64

// ---- scratch: __device__ globals, device-code references only ----
__device__ int   g_is64;
__device__ int   g_cnt[NN];       // in-degree (excl self-loop)
__device__ int   g_rowptr[NN];    // CSR row start
__device__ int   g_wpos[NN];      // fill cursor (copy of rowptr)
__device__ int   g_adj[NE];       // src indices grouped by dst
__device__ float g_dinv[NN];
__device__ float g_t1s[(size_t)NN * F1];  // (x @ W1^T) * dinv[row]
__device__ float g_agg1[(size_t)NN * F1]; // aggregated layer-1
__device__ float g_t2s[(size_t)NN * F2];  // (relu(agg1+b1) @ W2^T) * dinv[row]

// ---------------- dtype detection ----------------
__global__ void detect_kernel(const void* ei, int n, int e) {
    __shared__ int bad;
    if (threadIdx.x == 0) bad = 0;
    __syncthreads();
    const long long* p = (const long long*)ei;
    for (int i = threadIdx.x; i < 1024 && i < e; i += blockDim.x) {
        long long v = p[i];
        if (v < 0 || v >= n) bad = 1;
    }
    __syncthreads();
    if (threadIdx.x == 0) g_is64 = (bad == 0) ? 1 : 0;
}

__global__ void zero_cnt_kernel(int n) {
    int i = blockIdx.x * blockDim.x + threadIdx.x;
    if (i < n) g_cnt[i] = 0;
}

// histogram of dst (reads dst half of ei only)
__global__ void count_kernel(const void* ei, int e) {
    int i = blockIdx.x * blockDim.x + threadIdx.x;
    if (i >= e) return;
    int d = g_is64 ? (int)((const long long*)ei)[(size_t)e + i]
                   : ((const int*)ei)[(size_t)e + i];
    atomicAdd(&g_cnt[d], 1);
}

__global__ void dinv_kernel(int n) {
    int i = blockIdx.x * blockDim.x + threadIdx.x;
    if (i < n) g_dinv[i] = rsqrtf((float)(g_cnt[i] + 1));   // +1 self-loop
}

// single-block exclusive scan of g_cnt -> g_rowptr / g_wpos
__global__ void scan_kernel(int n) {
    __shared__ int sums[1024];
    const int tid = threadIdx.x;
    const int ITEMS = (n + 1023) / 1024;
    int start = tid * ITEMS;
    int end = min(start + ITEMS, n);
    int s = 0;
    for (int i = start; i < end; i++) s += g_cnt[i];
    sums[tid] = s;
    __syncthreads();
    // Hillis-Steele inclusive scan over 1024
    for (int off = 1; off < 1024; off <<= 1) {
        int v = (tid >= off) ? sums[tid - off] : 0;
        __syncthreads();
        sums[tid] += v;
        __syncthreads();
    }
    int prefix = (tid == 0) ? 0 : sums[tid - 1];
    for (int i = start; i < end; i++) {
        g_rowptr[i] = prefix;
        g_wpos[i]   = prefix;
        prefix += g_cnt[i];
    }
}

// fill adjacency (re-decode both halves of ei)
__global__ void fill_kernel(const void* ei, int e) {
    int i = blockIdx.x * blockDim.x + threadIdx.x;
    if (i >= e) return;
    int s, d;
    if (g_is64) {
        const long long* p = (const long long*)ei;
        s = (int)p[i];
        d = (int)p[(size_t)e + i];
    } else {
        const int* p = (const int*)ei;
        s = p[i];
        d = p[(size_t)e + i];
    }
    int pos = atomicAdd(&g_wpos[d], 1);
    g_adj[pos] = s;
}

// ---------------- SGEMM: t[r,c] = sum_k X[r,k] * W[c,k]; epilogue *= dinv[r] ----------------
template<bool LAYER1>
__global__ void gemm_kernel(const float* __restrict__ Xarg,
                            const float* __restrict__ W,
                            const float* __restrict__ bias,   // b1 (layer2 load fusion)
                            int n) {
    constexpr int FOUT = LAYER1 ? F1 : F2;
    constexpr int BM = 64;
    constexpr int BK = 16;
    constexpr int CG = FOUT / 4;
    constexpr int RG = 256 / CG;
    constexpr int TM = BM / RG;

    const float* X = LAYER1 ? Xarg : (const float*)g_agg1;
    float* outS = LAYER1 ? (float*)g_t1s : (float*)g_t2s;

    __shared__ float Xs[BM][BK];
    __shared__ float Ws[BK][FOUT + 4];

    const int tid = threadIdx.x;
    const int tx = tid % CG;
    const int ty = tid / CG;
    const int row0 = blockIdx.x * BM;

    float acc[TM][4];
#pragma unroll
    for (int i = 0; i < TM; i++) { acc[i][0]=acc[i][1]=acc[i][2]=acc[i][3]=0.f; }

#pragma unroll
    for (int k0 = 0; k0 < 128; k0 += BK) {
        {
            int r = tid >> 2;
            int c = (tid & 3) * 4;
            int gr = row0 + r;
            float4 v = make_float4(0.f, 0.f, 0.f, 0.f);
            if (gr < n) v = *(const float4*)&X[(size_t)gr * 128 + k0 + c];
            if (!LAYER1) {
                v.x = fmaxf(v.x + bias[k0 + c + 0], 0.f);
                v.y = fmaxf(v.y + bias[k0 + c + 1], 0.f);
                v.z = fmaxf(v.z + bias[k0 + c + 2], 0.f);
                v.w = fmaxf(v.w + bias[k0 + c + 3], 0.f);
            }
            *(float4*)&Xs[r][c] = v;
        }
#pragma unroll
        for (int t = tid; t < FOUT * (BK / 4); t += 256) {
            int c  = t >> 2;
            int kc = (t & 3) * 4;
            float4 v = *(const float4*)&W[(size_t)c * 128 + k0 + kc];
            Ws[kc + 0][c] = v.x; Ws[kc + 1][c] = v.y;
            Ws[kc + 2][c] = v.z; Ws[kc + 3][c] = v.w;
        }
        __syncthreads();

#pragma unroll
        for (int kk = 0; kk < BK; kk++) {
            float4 b = *(const float4*)&Ws[kk][tx * 4];
#pragma unroll
            for (int i = 0; i < TM; i++) {
                float a = Xs[ty * TM + i][kk];
                acc[i][0] += a * b.x; acc[i][1] += a * b.y;
                acc[i][2] += a * b.z; acc[i][3] += a * b.w;
            }
        }
        __syncthreads();
    }

#pragma unroll
    for (int i = 0; i < TM; i++) {
        int r = row0 + ty * TM + i;
        if (r < n) {
            float di = g_dinv[r];
            *(float4*)&outS[(size_t)r * FOUT + tx * 4] =
                make_float4(acc[i][0]*di, acc[i][1]*di, acc[i][2]*di, acc[i][3]*di);
        }
    }
}

// ---------------- CSR aggregation (atomic-free) ----------------
// agg1[dst] = dinv[dst] * ( t1s[dst] + sum_{src in adj[dst]} t1s[src] )
// one warp per dst; lane covers 4 floats (128 feats)
__global__ void agg1_kernel(int n) {
    int w = (blockIdx.x * blockDim.x + threadIdx.x) >> 5;
    if (w >= n) return;
    int lane = threadIdx.x & 31;
    int c = lane * 4;
    float4 acc = *(const float4*)&g_t1s[(size_t)w * F1 + c];   // self-loop
    int beg = g_rowptr[w];
    int cnt = g_cnt[w];
    for (int j = 0; j < cnt; j++) {
        int src = g_adj[beg + j];
        float4 v = *(const float4*)&g_t1s[(size_t)src * F1 + c];
        acc.x += v.x; acc.y += v.y; acc.z += v.z; acc.w += v.w;
    }
    float di = g_dinv[w];
    *(float4*)&g_agg1[(size_t)w * F1 + c] =
        make_float4(acc.x*di, acc.y*di, acc.z*di, acc.w*di);
}

// out[dst] = dinv[dst] * ( t2s[dst] + sum t2s[src] ) + b2 ; half-warp per dst (64 feats)
__global__ void agg2_kernel(const float* __restrict__ b2, float* __restrict__ out, int n) {
    int h = (blockIdx.x * blockDim.x + threadIdx.x) >> 4;
    if (h >= n) return;
    int lane = threadIdx.x & 15;
    int c = lane * 4;
    float4 acc = *(const float4*)&g_t2s[(size_t)h * F2 + c];   // self-loop
    int beg = g_rowptr[h];
    int cnt = g_cnt[h];
    for (int j = 0; j < cnt; j++) {
        int src = g_adj[beg + j];
        float4 v = *(const float4*)&g_t2s[(size_t)src * F2 + c];
        acc.x += v.x; acc.y += v.y; acc.z += v.z; acc.w += v.w;
    }
    float di = g_dinv[h];
    *(float4*)&out[(size_t)h * F2 + c] =
        make_float4(acc.x*di + b2[c+0], acc.y*di + b2[c+1],
                    acc.z*di + b2[c+2], acc.w*di + b2[c+3]);
}

// ---------------- launch ----------------
extern "C" void kernel_launch(void* const* d_in, const int* in_sizes, int n_in,
                              void* d_out, int out_size) {
    const float* x  = (const float*)d_in[0];
    const void*  ei = d_in[1];
    const float* W1 = (const float*)d_in[2];
    const float* b1 = (const float*)d_in[3];
    const float* W2 = (const float*)d_in[4];
    const float* b2 = (const float*)d_in[5];
    float* out = (float*)d_out;

    const int n = in_sizes[0] / F1;       // 100000
    const int e = in_sizes[1] / 2;        // 1600000

    const int T = 256;
    // CSR build + norms
    detect_kernel<<<1, 256>>>(ei, n, e);
    zero_cnt_kernel<<<(n + T - 1) / T, T>>>(n);
    count_kernel<<<(e + T - 1) / T, T>>>(ei, e);
    dinv_kernel<<<(n + T - 1) / T, T>>>(n);
    scan_kernel<<<1, 1024>>>(n);
    fill_kernel<<<(e + T - 1) / T, T>>>(ei, e);

    // layer 1
    gemm_kernel<true><<<(n + 63) / 64, 256>>>(x, W1, nullptr, n);
    agg1_kernel<<<(n * 32 + T - 1) / T, T>>>(n);

    // layer 2
    gemm_kernel<false><<<(n + 63) / 64, 256>>>(nullptr, W2, b1, n);
    agg2_kernel<<<(n * 16 + T - 1) / T, T>>>(b2, out, n);
}